// round 4
// baseline (speedup 1.0000x reference)
#include <cuda_runtime.h>
#include <cuda_bf16.h>
#include <math.h>

// ---------------- problem constants ----------------
#define BATCH 512
#define HH 14
#define WW 14
#define DIN 512
#define EDIM 64
#define KCODES 256
#define NPIX (BATCH*HH*WW)          // 100352
#define NTOK (BATCH*4)              // 2048
#define H1 128                      // 2*EDIM

// output layout (float32, concatenated in reference return order)
#define OUT_DEC 0
#define OUT_PPL ((size_t)NPIX*DIN)            // 51380224
#define OUT_CMT (OUT_PPL+1)
#define OUT_IDX (OUT_PPL+2)

// ---------------- scratch (static device memory; no allocations) ----------------
__device__ float g_H[(size_t)NPIX*H1];      // gelu(delta@W1+b1), 51.4 MB
__device__ float g_Hbar[NTOK*H1];           // pooled hidden
__device__ float g_S[NTOK*DIN];             // decoder output per token
__device__ int   g_idx[NTOK];
__device__ int   g_counts[KCODES];
__device__ float g_loss;

__device__ __forceinline__ float gelu_exact(float x) {
    return 0.5f * x * (1.0f + erff(x * 0.70710678118654752440f));
}

// ---------------- kernel 0: zero accumulators ----------------
__global__ void k_init() {
    int t = threadIdx.x;
    if (t < KCODES) g_counts[t] = 0;
    if (t == 0) g_loss = 0.0f;
}

// ---------------- kernel 1: fused delta + GEMM1 + GELU ----------------
// H[p, j] = gelu( (t1[p,:]-t0[p,:]) @ W1[:, j] + b1[j] ),  p in [0,100352), j in [0,128)
// 128-row x 128-col block tile, 256 threads, 8x8 register micro-tile, K chunks of 16.
__global__ __launch_bounds__(256) void k_enc1(const float* __restrict__ t0,
                                              const float* __restrict__ t1,
                                              const float* __restrict__ w1,
                                              const float* __restrict__ b1) {
    __shared__ float As[16][128];   // [k][row]  (delta, transposed)
    __shared__ float Bs[16][128];   // [k][col]  (W1)
    const int tid = threadIdx.x;
    const int tx = tid & 15, ty = tid >> 4;
    const int r0 = ty * 8, c0 = tx * 8;
    const int p0 = blockIdx.x * 128;

    float acc[8][8];
#pragma unroll
    for (int i = 0; i < 8; i++)
#pragma unroll
        for (int j = 0; j < 8; j++) acc[i][j] = 0.0f;

    for (int kc = 0; kc < DIN; kc += 16) {
        // stage delta tile (128 rows x 16 k), transposed into As[k][row]
#pragma unroll
        for (int i = 0; i < 2; i++) {
            int li  = tid + i * 256;      // 0..511 float4s
            int row = li >> 2;
            int kk  = (li & 3) << 2;
            size_t g = (size_t)(p0 + row) * DIN + kc + kk;
            float4 a1 = *(const float4*)(t1 + g);
            float4 a0 = *(const float4*)(t0 + g);
            As[kk + 0][row] = a1.x - a0.x;
            As[kk + 1][row] = a1.y - a0.y;
            As[kk + 2][row] = a1.z - a0.z;
            As[kk + 3][row] = a1.w - a0.w;
        }
        // stage W1 tile (16 k x 128 cols)
#pragma unroll
        for (int i = 0; i < 2; i++) {
            int li = tid + i * 256;       // 0..511 float4s
            int kk = li >> 5;
            int cc = (li & 31) << 2;
            *(float4*)&Bs[kk][cc] = *(const float4*)(w1 + (size_t)(kc + kk) * H1 + cc);
        }
        __syncthreads();
#pragma unroll
        for (int k = 0; k < 16; k++) {
            float4 av0 = *(const float4*)&As[k][r0];
            float4 av1 = *(const float4*)&As[k][r0 + 4];
            float4 bv0 = *(const float4*)&Bs[k][c0];
            float4 bv1 = *(const float4*)&Bs[k][c0 + 4];
            float a[8] = {av0.x, av0.y, av0.z, av0.w, av1.x, av1.y, av1.z, av1.w};
            float b[8] = {bv0.x, bv0.y, bv0.z, bv0.w, bv1.x, bv1.y, bv1.z, bv1.w};
#pragma unroll
            for (int i = 0; i < 8; i++)
#pragma unroll
                for (int j = 0; j < 8; j++) acc[i][j] = fmaf(a[i], b[j], acc[i][j]);
        }
        __syncthreads();
    }

    float bias[8];
#pragma unroll
    for (int j = 0; j < 8; j++) bias[j] = b1[c0 + j];
#pragma unroll
    for (int i = 0; i < 8; i++) {
        size_t row = (size_t)(p0 + r0 + i);
        float v[8];
#pragma unroll
        for (int j = 0; j < 8; j++) v[j] = gelu_exact(acc[i][j] + bias[j]);
        *(float4*)&g_H[row * H1 + c0]     = make_float4(v[0], v[1], v[2], v[3]);
        *(float4*)&g_H[row * H1 + c0 + 4] = make_float4(v[4], v[5], v[6], v[7]);
    }
}

// ---------------- kernel 2: 7x7 block-mean pooling of H ----------------
// token t = b*4 + gy*2 + gx ; Hbar[t,j] = mean over 49 pixels of H[p,j]
__global__ __launch_bounds__(128) void k_pool() {
    int t = blockIdx.x;
    int j = threadIdx.x;
    int b = t >> 2, g = t & 3, gy = g >> 1, gx = g & 1;
    float s = 0.0f;
#pragma unroll
    for (int dy = 0; dy < 7; dy++) {
        int y = gy * 7 + dy;
#pragma unroll
        for (int dx = 0; dx < 7; dx++) {
            int x = gx * 7 + dx;
            size_t pix = (size_t)((b * HH + y) * WW + x);
            s += g_H[pix * H1 + j];
        }
    }
    g_Hbar[t * H1 + j] = s * (1.0f / 49.0f);
}

// ---------------- kernel 3: GEMM2 (pool-commuted) + VQ argmin + loss/count ----------------
__global__ __launch_bounds__(256) void k_vq(const float* __restrict__ w2,
                                            const float* __restrict__ b2,
                                            const float* __restrict__ cb) {
    __shared__ float hb[H1];
    __shared__ float fl[EDIM];
    __shared__ float sd[256];
    __shared__ int   si[256];
    int t = blockIdx.x;
    int tid = threadIdx.x;

    if (tid < H1) hb[tid] = g_Hbar[t * H1 + tid];
    __syncthreads();
    if (tid < EDIM) {
        float s = b2[tid];
#pragma unroll 8
        for (int k = 0; k < H1; k++) s = fmaf(hb[k], w2[k * EDIM + tid], s);
        fl[tid] = s;
    }
    __syncthreads();

    float d = 0.0f;
    const float* crow = cb + tid * EDIM;
#pragma unroll 8
    for (int j = 0; j < EDIM; j++) {
        float df = fl[j] - crow[j];
        d = fmaf(df, df, d);
    }
    sd[tid] = d; si[tid] = tid;
    __syncthreads();
    for (int s = 128; s > 0; s >>= 1) {
        if (tid < s) {
            float od = sd[tid + s]; int oi = si[tid + s];
            if (od < sd[tid] || (od == sd[tid] && oi < si[tid])) { sd[tid] = od; si[tid] = oi; }
        }
        __syncthreads();
    }
    if (tid == 0) {
        g_idx[t] = si[0];
        atomicAdd(&g_counts[si[0]], 1);
        atomicAdd(&g_loss, sd[0]);
    }
}

// ---------------- kernel 4: perplexity + commitment + indices ----------------
__global__ __launch_bounds__(256) void k_fin(float* __restrict__ out) {
    __shared__ float r[256];
    int tid = threadIdx.x;
    float p = (float)g_counts[tid] * (1.0f / (float)NTOK);
    r[tid] = p * logf(p + 1e-10f);
    __syncthreads();
    for (int s = 128; s > 0; s >>= 1) {
        if (tid < s) r[tid] += r[tid + s];
        __syncthreads();
    }
    if (tid == 0) {
        out[OUT_PPL] = expf(-r[0]);
        out[OUT_CMT] = g_loss * (1.0f / (float)(NTOK * EDIM));
    }
    for (int i = tid; i < NTOK; i += 256) out[OUT_IDX + i] = (float)g_idx[i];
}

// ---------------- kernel 5: decoder MLP (8 tokens per block) ----------------
// q = codebook[idx]; hd = gelu(q@dw1+db1); S = hd@dw2+db2
__global__ __launch_bounds__(256) void k_dec(const float* __restrict__ dw1,
                                             const float* __restrict__ db1,
                                             const float* __restrict__ dw2,
                                             const float* __restrict__ db2,
                                             const float* __restrict__ cb) {
    __shared__ float q[8][EDIM];
    __shared__ float hd[8][H1];
    int tid = threadIdx.x;
    int tb = blockIdx.x * 8;

    for (int li = tid; li < 8 * EDIM; li += 256) {
        int tt = li >> 6, j = li & 63;
        q[tt][j] = cb[g_idx[tb + tt] * EDIM + j];
    }
    __syncthreads();
#pragma unroll
    for (int i = 0; i < 4; i++) {
        int li = tid + i * 256;
        int tt = li >> 7, j = li & 127;
        float s = db1[j];
#pragma unroll 8
        for (int k = 0; k < EDIM; k++) s = fmaf(q[tt][k], dw1[k * H1 + j], s);
        hd[tt][j] = gelu_exact(s);
    }
    __syncthreads();

    float a0[8], a1[8];
#pragma unroll
    for (int tt = 0; tt < 8; tt++) { a0[tt] = 0.0f; a1[tt] = 0.0f; }
#pragma unroll 4
    for (int k = 0; k < H1; k++) {
        float w0 = dw2[k * DIN + tid];
        float w1v = dw2[k * DIN + 256 + tid];
#pragma unroll
        for (int tt = 0; tt < 8; tt++) {
            float h = hd[tt][k];
            a0[tt] = fmaf(h, w0, a0[tt]);
            a1[tt] = fmaf(h, w1v, a1[tt]);
        }
    }
    float bb0 = db2[tid], bb1 = db2[tid + 256];
#pragma unroll
    for (int tt = 0; tt < 8; tt++) {
        g_S[(size_t)(tb + tt) * DIN + tid]       = a0[tt] + bb0;
        g_S[(size_t)(tb + tt) * DIN + 256 + tid] = a1[tt] + bb1;
    }
}

// ---------------- kernel 6: 2x2 -> 14x14 bilinear (half-pixel, clamped) ----------------
// block = (b, y); row-blend A/B then 14 x-columns
__global__ __launch_bounds__(256) void k_up(float* __restrict__ out) {
    __shared__ float Arow[DIN], Brow[DIN];
    int b = blockIdx.x, y = blockIdx.y;
    int tid = threadIdx.x;

    float sy = (y + 0.5f) * (1.0f / 7.0f) - 0.5f;
    int iy0 = (int)floorf(sy);
    float fy = sy - (float)iy0;
    int y0 = min(max(iy0, 0), 1);
    int y1 = min(max(iy0 + 1, 0), 1);

    const float* S0a = &g_S[(size_t)(b * 4 + y0 * 2 + 0) * DIN];
    const float* S1a = &g_S[(size_t)(b * 4 + y1 * 2 + 0) * DIN];
    const float* S0b = &g_S[(size_t)(b * 4 + y0 * 2 + 1) * DIN];
    const float* S1b = &g_S[(size_t)(b * 4 + y1 * 2 + 1) * DIN];
    float wy0 = 1.0f - fy;
    for (int c = tid; c < DIN; c += 256) {
        Arow[c] = wy0 * S0a[c] + fy * S1a[c];
        Brow[c] = wy0 * S0b[c] + fy * S1b[c];
    }
    __syncthreads();

#pragma unroll
    for (int x = 0; x < 14; x++) {
        float sx = (x + 0.5f) * (1.0f / 7.0f) - 0.5f;
        int ix0 = (int)floorf(sx);
        float fx = sx - (float)ix0;
        int x0 = min(max(ix0, 0), 1);
        int x1 = min(max(ix0 + 1, 0), 1);
        float wx0 = 1.0f - fx;
        float* o = out + ((size_t)((b * HH + y) * WW + x)) * DIN;
        for (int c = tid; c < DIN; c += 256) {
            float v0 = x0 ? Brow[c] : Arow[c];
            float v1 = x1 ? Brow[c] : Arow[c];
            o[c] = wx0 * v0 + fx * v1;
        }
    }
}

// ---------------- launch ----------------
extern "C" void kernel_launch(void* const* d_in, const int* in_sizes, int n_in,
                              void* d_out, int out_size) {
    const float* t0  = (const float*)d_in[0];
    const float* t1  = (const float*)d_in[1];
    const float* ew1 = (const float*)d_in[2];
    const float* eb1 = (const float*)d_in[3];
    const float* ew2 = (const float*)d_in[4];
    const float* eb2 = (const float*)d_in[5];
    const float* dw1 = (const float*)d_in[6];
    const float* db1 = (const float*)d_in[7];
    const float* dw2 = (const float*)d_in[8];
    const float* db2 = (const float*)d_in[9];
    const float* cb  = (const float*)d_in[10];
    float* out = (float*)d_out;

    k_init<<<1, 256>>>();
    k_enc1<<<NPIX / 128, 256>>>(t0, t1, ew1, eb1);
    k_pool<<<NTOK, 128>>>();
    k_vq<<<NTOK, 256>>>(ew2, eb2, cb);
    k_fin<<<1, 256>>>(out);
    k_dec<<<NTOK / 8, 256>>>(dw1, db1, dw2, db2, cb);
    k_up<<<dim3(BATCH, HH), 256>>>(out);
}

// round 5
// speedup vs baseline: 1.1808x; 1.1808x over previous
#include <cuda_runtime.h>
#include <cuda_bf16.h>
#include <math.h>

// ---------------- problem constants ----------------
#define BATCH 512
#define HH 14
#define WW 14
#define DIN 512
#define EDIM 64
#define KCODES 256
#define NPIX (BATCH*HH*WW)          // 100352
#define NTOK (BATCH*4)              // 2048
#define H1 128                      // 2*EDIM

// output layout (float32, concatenated in reference return order)
#define OUT_DEC 0
#define OUT_PPL ((size_t)NPIX*DIN)            // 51380224
#define OUT_CMT (OUT_PPL+1)
#define OUT_IDX (OUT_PPL+2)

typedef unsigned long long u64;

// ---------------- scratch (static device memory; no allocations) ----------------
__device__ float g_H[(size_t)NPIX*H1];      // gelu(delta@W1+b1), 51.4 MB
__device__ float g_Hbar[NTOK*H1];           // pooled hidden
__device__ float g_S[NTOK*DIN];             // decoder output per token
__device__ int   g_idx[NTOK];
__device__ int   g_counts[KCODES];
__device__ float g_loss;

__device__ __forceinline__ float gelu_exact(float x) {
    return 0.5f * x * (1.0f + erff(x * 0.70710678118654752440f));
}

__device__ __forceinline__ u64 pack2(float lo, float hi) {
    u64 r; asm("mov.b64 %0, {%1, %2};" : "=l"(r) : "f"(lo), "f"(hi)); return r;
}
__device__ __forceinline__ void unpack2(u64 v, float& lo, float& hi) {
    asm("mov.b64 {%0, %1}, %2;" : "=f"(lo), "=f"(hi) : "l"(v));
}
__device__ __forceinline__ void ffma2(u64& d, u64 a, u64 b) {
    asm("fma.rn.f32x2 %0, %1, %2, %0;" : "+l"(d) : "l"(a), "l"(b));
}

// ---------------- kernel 0: zero accumulators ----------------
__global__ void k_init() {
    int t = threadIdx.x;
    if (t < KCODES) g_counts[t] = 0;
    if (t == 0) g_loss = 0.0f;
}

// ---------------- kernel 1: fused delta + GEMM1 + GELU (packed f32x2 FMA) ----------------
// H[p, j] = gelu( (t1[p,:]-t0[p,:]) @ W1[:, j] + b1[j] )
// 128x128 block tile, 256 threads, 8x8 micro-tile held as 8x4 packed f32x2 pairs.
__global__ __launch_bounds__(256) void k_enc1(const float* __restrict__ t0,
                                              const float* __restrict__ t1,
                                              const float* __restrict__ w1,
                                              const float* __restrict__ b1) {
    __shared__ float As[16][128];   // [k][row]  (delta, transposed)
    __shared__ float Bs[16][128];   // [k][col]  (W1)
    const int tid = threadIdx.x;
    const int tx = tid & 15, ty = tid >> 4;
    const int r0 = ty * 8, c0 = tx * 8;
    const int p0 = blockIdx.x * 128;

    u64 acc2[8][4];                 // acc2[i][jp] = (acc[i][2jp], acc[i][2jp+1])
#pragma unroll
    for (int i = 0; i < 8; i++)
#pragma unroll
        for (int j = 0; j < 4; j++) acc2[i][j] = 0ull;   // bits of (+0.f, +0.f)

    for (int kc = 0; kc < DIN; kc += 16) {
        // stage delta tile (128 rows x 16 k), transposed into As[k][row]
#pragma unroll
        for (int i = 0; i < 2; i++) {
            int li  = tid + i * 256;      // 0..511 float4s
            int row = li >> 2;
            int kk  = (li & 3) << 2;
            size_t g = (size_t)(p0 + row) * DIN + kc + kk;
            float4 a1 = *(const float4*)(t1 + g);
            float4 a0 = *(const float4*)(t0 + g);
            As[kk + 0][row] = a1.x - a0.x;
            As[kk + 1][row] = a1.y - a0.y;
            As[kk + 2][row] = a1.z - a0.z;
            As[kk + 3][row] = a1.w - a0.w;
        }
        // stage W1 tile (16 k x 128 cols)
#pragma unroll
        for (int i = 0; i < 2; i++) {
            int li = tid + i * 256;       // 0..511 float4s
            int kk = li >> 5;
            int cc = (li & 31) << 2;
            *(float4*)&Bs[kk][cc] = *(const float4*)(w1 + (size_t)(kc + kk) * H1 + cc);
        }
        __syncthreads();
#pragma unroll
        for (int k = 0; k < 16; k++) {
            float4 av0 = *(const float4*)&As[k][r0];
            float4 av1 = *(const float4*)&As[k][r0 + 4];
            ulonglong2 bv0 = *(const ulonglong2*)&Bs[k][c0];     // (b0,b1),(b2,b3)
            ulonglong2 bv1 = *(const ulonglong2*)&Bs[k][c0 + 4]; // (b4,b5),(b6,b7)
            float a[8] = {av0.x, av0.y, av0.z, av0.w, av1.x, av1.y, av1.z, av1.w};
#pragma unroll
            for (int i = 0; i < 8; i++) {
                u64 aa = pack2(a[i], a[i]);
                ffma2(acc2[i][0], aa, bv0.x);
                ffma2(acc2[i][1], aa, bv0.y);
                ffma2(acc2[i][2], aa, bv1.x);
                ffma2(acc2[i][3], aa, bv1.y);
            }
        }
        __syncthreads();
    }

    float bias[8];
#pragma unroll
    for (int j = 0; j < 8; j++) bias[j] = b1[c0 + j];
#pragma unroll
    for (int i = 0; i < 8; i++) {
        size_t row = (size_t)(p0 + r0 + i);
        float v[8];
#pragma unroll
        for (int jp = 0; jp < 4; jp++) {
            float lo, hi;
            unpack2(acc2[i][jp], lo, hi);
            v[2 * jp]     = gelu_exact(lo + bias[2 * jp]);
            v[2 * jp + 1] = gelu_exact(hi + bias[2 * jp + 1]);
        }
        *(float4*)&g_H[row * H1 + c0]     = make_float4(v[0], v[1], v[2], v[3]);
        *(float4*)&g_H[row * H1 + c0 + 4] = make_float4(v[4], v[5], v[6], v[7]);
    }
}

// ---------------- kernel 2: 7x7 block-mean pooling of H ----------------
__global__ __launch_bounds__(128) void k_pool() {
    int t = blockIdx.x;
    int j = threadIdx.x;
    int b = t >> 2, g = t & 3, gy = g >> 1, gx = g & 1;
    float s = 0.0f;
#pragma unroll
    for (int dy = 0; dy < 7; dy++) {
        int y = gy * 7 + dy;
#pragma unroll
        for (int dx = 0; dx < 7; dx++) {
            int x = gx * 7 + dx;
            size_t pix = (size_t)((b * HH + y) * WW + x);
            s += g_H[pix * H1 + j];
        }
    }
    g_Hbar[t * H1 + j] = s * (1.0f / 49.0f);
}

// ---------------- kernel 3: GEMM2 + VQ (blocked, shared-codebook, coalesced) ----------------
// 64 blocks x 256 threads, 32 tokens per block.
// smem: cbT[64][257] transposed+padded codebook, hbs[32][128], fs[32][65], cn[256], fnorm[32]
#define VQ_TOKS 32
#define CBT_LD 257
#define FS_LD 65
#define SMEM_VQ_FLOATS (64*CBT_LD + VQ_TOKS*H1 + VQ_TOKS*FS_LD + KCODES + VQ_TOKS)
#define SMEM_VQ_BYTES (SMEM_VQ_FLOATS * 4)

__global__ __launch_bounds__(256) void k_vq2(const float* __restrict__ w2,
                                             const float* __restrict__ b2,
                                             const float* __restrict__ cb) {
    extern __shared__ float sm[];
    float* cbT   = sm;                         // [64][257]
    float* hbs   = cbT + 64 * CBT_LD;          // [32][128]
    float* fs    = hbs + VQ_TOKS * H1;         // [32][65]
    float* cn    = fs + VQ_TOKS * FS_LD;       // [256]
    float* fnorm = cn + KCODES;                // [32]

    const int tid = threadIdx.x;
    const int tok0 = blockIdx.x * VQ_TOKS;

    // stage codebook (transposed, padded) and Hbar slice — fully coalesced global reads
    for (int li = tid; li < KCODES * EDIM; li += 256) {
        int c = li >> 6, j = li & 63;
        cbT[j * CBT_LD + c] = cb[li];
    }
    for (int li = tid; li < VQ_TOKS * H1; li += 256) {
        hbs[li] = g_Hbar[tok0 * H1 + li];
    }
    __syncthreads();

    // code norms: thread c, reads cbT[j][c] (consecutive banks across lanes)
    {
        float s = 0.0f;
#pragma unroll 8
        for (int j = 0; j < EDIM; j++) {
            float v = cbT[j * CBT_LD + tid];
            s = fmaf(v, v, s);
        }
        cn[tid] = s;
    }

    // phase 1: flat = Hbar @ w2 + b2. thread = (dim j, token-group tg of 8)
    {
        const int j = tid & 63, tg = tid >> 6;
        float acc[8];
        float bj = b2[j];
#pragma unroll
        for (int u = 0; u < 8; u++) acc[u] = bj;
#pragma unroll 4
        for (int k = 0; k < H1; k++) {
            float wv = __ldg(&w2[k * EDIM + j]);     // warp: 32 consecutive floats
#pragma unroll
            for (int u = 0; u < 8; u++)
                acc[u] = fmaf(hbs[(tg * 8 + u) * H1 + k], wv, acc[u]);  // broadcast
        }
#pragma unroll
        for (int u = 0; u < 8; u++) fs[(tg * 8 + u) * FS_LD + j] = acc[u];
    }
    __syncthreads();

    // fnorm per token
    if (tid < VQ_TOKS) {
        float s = 0.0f;
#pragma unroll 8
        for (int j = 0; j < EDIM; j++) {
            float v = fs[tid * FS_LD + j];
            s = fmaf(v, v, s);
        }
        fnorm[tid] = s;
    }
    __syncthreads();

    // phase 2: distances + argmin. warp w -> tokens 4w..4w+3, lane l -> codes l+32i
    const int w = tid >> 5, l = tid & 31;
    const int tb = w * 4;
    float dot[4][8];
#pragma unroll
    for (int t = 0; t < 4; t++)
#pragma unroll
        for (int i = 0; i < 8; i++) dot[t][i] = 0.0f;

#pragma unroll 4
    for (int j = 0; j < EDIM; j++) {
        float fj[4];
#pragma unroll
        for (int t = 0; t < 4; t++) fj[t] = fs[(tb + t) * FS_LD + j];   // broadcast
        float cv[8];
#pragma unroll
        for (int i = 0; i < 8; i++) cv[i] = cbT[j * CBT_LD + l + 32 * i]; // conflict-free
#pragma unroll
        for (int t = 0; t < 4; t++)
#pragma unroll
            for (int i = 0; i < 8; i++) dot[t][i] = fmaf(fj[t], cv[i], dot[t][i]);
    }

#pragma unroll
    for (int t = 0; t < 4; t++) {
        float bd = 3.4e38f; int bi = 0;
#pragma unroll
        for (int i = 0; i < 8; i++) {
            int c = l + 32 * i;
            float d = fmaf(-2.0f, dot[t][i], cn[c]);
            if (d < bd) { bd = d; bi = c; }
        }
        for (int off = 16; off > 0; off >>= 1) {
            float od = __shfl_down_sync(0xffffffffu, bd, off);
            int   oi = __shfl_down_sync(0xffffffffu, bi, off);
            if (od < bd || (od == bd && oi < bi)) { bd = od; bi = oi; }
        }
        if (l == 0) {
            int tok = tok0 + tb + t;
            g_idx[tok] = bi;
            atomicAdd(&g_counts[bi], 1);
            atomicAdd(&g_loss, fnorm[tb + t] + bd);
        }
    }
}

// ---------------- kernel 4: perplexity + commitment + indices ----------------
__global__ __launch_bounds__(256) void k_fin(float* __restrict__ out) {
    __shared__ float r[256];
    int tid = threadIdx.x;
    float p = (float)g_counts[tid] * (1.0f / (float)NTOK);
    r[tid] = p * logf(p + 1e-10f);
    __syncthreads();
    for (int s = 128; s > 0; s >>= 1) {
        if (tid < s) r[tid] += r[tid + s];
        __syncthreads();
    }
    if (tid == 0) {
        out[OUT_PPL] = expf(-r[0]);
        out[OUT_CMT] = g_loss * (1.0f / (float)(NTOK * EDIM));
    }
    for (int i = tid; i < NTOK; i += 256) out[OUT_IDX + i] = (float)g_idx[i];
}

// ---------------- kernel 5: decoder MLP (8 tokens per block) ----------------
__global__ __launch_bounds__(256) void k_dec(const float* __restrict__ dw1,
                                             const float* __restrict__ db1,
                                             const float* __restrict__ dw2,
                                             const float* __restrict__ db2,
                                             const float* __restrict__ cb) {
    __shared__ float q[8][EDIM];
    __shared__ float hd[8][H1];
    int tid = threadIdx.x;
    int tb = blockIdx.x * 8;

    for (int li = tid; li < 8 * EDIM; li += 256) {
        int tt = li >> 6, j = li & 63;
        q[tt][j] = cb[g_idx[tb + tt] * EDIM + j];
    }
    __syncthreads();
#pragma unroll
    for (int i = 0; i < 4; i++) {
        int li = tid + i * 256;
        int tt = li >> 7, j = li & 127;
        float s = db1[j];
#pragma unroll 8
        for (int k = 0; k < EDIM; k++) s = fmaf(q[tt][k], dw1[k * H1 + j], s);
        hd[tt][j] = gelu_exact(s);
    }
    __syncthreads();

    float a0[8], a1[8];
#pragma unroll
    for (int tt = 0; tt < 8; tt++) { a0[tt] = 0.0f; a1[tt] = 0.0f; }
#pragma unroll 4
    for (int k = 0; k < H1; k++) {
        float w0 = dw2[k * DIN + tid];
        float w1v = dw2[k * DIN + 256 + tid];
#pragma unroll
        for (int tt = 0; tt < 8; tt++) {
            float h = hd[tt][k];
            a0[tt] = fmaf(h, w0, a0[tt]);
            a1[tt] = fmaf(h, w1v, a1[tt]);
        }
    }
    float bb0 = db2[tid], bb1 = db2[tid + 256];
#pragma unroll
    for (int tt = 0; tt < 8; tt++) {
        g_S[(size_t)(tb + tt) * DIN + tid]       = a0[tt] + bb0;
        g_S[(size_t)(tb + tt) * DIN + 256 + tid] = a1[tt] + bb1;
    }
}

// ---------------- kernel 6: 2x2 -> 14x14 bilinear (half-pixel, clamped) ----------------
__global__ __launch_bounds__(256) void k_up(float* __restrict__ out) {
    __shared__ float Arow[DIN], Brow[DIN];
    int b = blockIdx.x, y = blockIdx.y;
    int tid = threadIdx.x;

    float sy = (y + 0.5f) * (1.0f / 7.0f) - 0.5f;
    int iy0 = (int)floorf(sy);
    float fy = sy - (float)iy0;
    int y0 = min(max(iy0, 0), 1);
    int y1 = min(max(iy0 + 1, 0), 1);

    const float* S0a = &g_S[(size_t)(b * 4 + y0 * 2 + 0) * DIN];
    const float* S1a = &g_S[(size_t)(b * 4 + y1 * 2 + 0) * DIN];
    const float* S0b = &g_S[(size_t)(b * 4 + y0 * 2 + 1) * DIN];
    const float* S1b = &g_S[(size_t)(b * 4 + y1 * 2 + 1) * DIN];
    float wy0 = 1.0f - fy;
    for (int c = tid; c < DIN; c += 256) {
        Arow[c] = wy0 * S0a[c] + fy * S1a[c];
        Brow[c] = wy0 * S0b[c] + fy * S1b[c];
    }
    __syncthreads();

#pragma unroll
    for (int x = 0; x < 14; x++) {
        float sx = (x + 0.5f) * (1.0f / 7.0f) - 0.5f;
        int ix0 = (int)floorf(sx);
        float fx = sx - (float)ix0;
        int x0 = min(max(ix0, 0), 1);
        int x1 = min(max(ix0 + 1, 0), 1);
        float wx0 = 1.0f - fx;
        float* o = out + ((size_t)((b * HH + y) * WW + x)) * DIN;
        for (int c = tid; c < DIN; c += 256) {
            float v0 = x0 ? Brow[c] : Arow[c];
            float v1 = x1 ? Brow[c] : Arow[c];
            o[c] = wx0 * v0 + fx * v1;
        }
    }
}

// ---------------- launch ----------------
extern "C" void kernel_launch(void* const* d_in, const int* in_sizes, int n_in,
                              void* d_out, int out_size) {
    const float* t0  = (const float*)d_in[0];
    const float* t1  = (const float*)d_in[1];
    const float* ew1 = (const float*)d_in[2];
    const float* eb1 = (const float*)d_in[3];
    const float* ew2 = (const float*)d_in[4];
    const float* eb2 = (const float*)d_in[5];
    const float* dw1 = (const float*)d_in[6];
    const float* db1 = (const float*)d_in[7];
    const float* dw2 = (const float*)d_in[8];
    const float* db2 = (const float*)d_in[9];
    const float* cb  = (const float*)d_in[10];
    float* out = (float*)d_out;

    cudaFuncSetAttribute(k_vq2, cudaFuncAttributeMaxDynamicSharedMemorySize, SMEM_VQ_BYTES);

    k_init<<<1, 256>>>();
    k_enc1<<<NPIX / 128, 256>>>(t0, t1, ew1, eb1);
    k_pool<<<NTOK, 128>>>();
    k_vq2<<<NTOK / VQ_TOKS, 256, SMEM_VQ_BYTES>>>(ew2, eb2, cb);
    k_fin<<<1, 256>>>(out);
    k_dec<<<NTOK / 8, 256>>>(dw1, db1, dw2, db2, cb);
    k_up<<<dim3(BATCH, HH), 256>>>(out);
}

// round 8
// speedup vs baseline: 2.0381x; 1.7260x over previous
#include <cuda_runtime.h>
#include <cuda_bf16.h>
#include <math.h>
#include <stdint.h>

// ---------------- problem constants ----------------
#define BATCH 512
#define HH 14
#define WW 14
#define DIN 512
#define EDIM 64
#define KCODES 256
#define NPIX (BATCH*HH*WW)          // 100352
#define NTOK (BATCH*4)              // 2048
#define H1 128                      // 2*EDIM

#define OUT_PPL ((size_t)NPIX*DIN)
#define OUT_CMT (OUT_PPL+1)
#define OUT_IDX (OUT_PPL+2)

// ---------------- scratch (static device memory; no allocations) ----------------
__device__ float g_H[(size_t)NPIX*H1];      // gelu(delta@W1+b1)
__device__ float g_Hbar[NTOK*H1];
__device__ float g_S[NTOK*DIN];
__device__ int   g_idx[NTOK];
__device__ int   g_counts[KCODES];
__device__ float g_loss;
// W1^T split into bf16 hi/lo: [n=128][k=512]
__device__ __nv_bfloat16 g_w1t_hi[H1*DIN];
__device__ __nv_bfloat16 g_w1t_lo[H1*DIN];

__device__ __forceinline__ float gelu_exact(float x) {
    return 0.5f * x * (1.0f + erff(x * 0.70710678118654752440f));
}

__device__ __forceinline__ uint32_t smem_u32(const void* p) {
    uint32_t a;
    asm("{ .reg .u64 t; cvta.to.shared.u64 t, %1; cvt.u32.u64 %0, t; }" : "=r"(a) : "l"(p));
    return a;
}

// baseline-PTX tensor ops (valid on plain sm_103 — no 'a' features)
__device__ __forceinline__ void ldsm_x4(uint32_t* r, uint32_t addr) {
    asm volatile("ldmatrix.sync.aligned.m8n8.x4.shared.b16 {%0,%1,%2,%3}, [%4];"
                 : "=r"(r[0]), "=r"(r[1]), "=r"(r[2]), "=r"(r[3]) : "r"(addr));
}
__device__ __forceinline__ void ldsm_x2(uint32_t* r, uint32_t addr) {
    asm volatile("ldmatrix.sync.aligned.m8n8.x2.shared.b16 {%0,%1}, [%2];"
                 : "=r"(r[0]), "=r"(r[1]) : "r"(addr));
}
__device__ __forceinline__ void mma_bf16(float* d, const uint32_t* a, const uint32_t* b) {
    asm volatile("mma.sync.aligned.m16n8k16.row.col.f32.bf16.bf16.f32 "
                 "{%0,%1,%2,%3}, {%4,%5,%6,%7}, {%8,%9}, {%0,%1,%2,%3};"
                 : "+f"(d[0]), "+f"(d[1]), "+f"(d[2]), "+f"(d[3])
                 : "r"(a[0]), "r"(a[1]), "r"(a[2]), "r"(a[3]), "r"(b[0]), "r"(b[1]));
}
__device__ __forceinline__ uint32_t pk_bf16(__nv_bfloat16 a, __nv_bfloat16 b) {
    return (uint32_t)__bfloat16_as_ushort(a) | ((uint32_t)__bfloat16_as_ushort(b) << 16);
}

// ---------------- kernel 0: zero accumulators ----------------
__global__ void k_init() {
    int t = threadIdx.x;
    if (t < KCODES) g_counts[t] = 0;
    if (t == 0) g_loss = 0.0f;
}

// ---------------- kernel 0b: pre-split W1^T into bf16 hi/lo ----------------
__global__ __launch_bounds__(256) void k_prep(const float* __restrict__ w1) {
    int idx = blockIdx.x * 256 + threadIdx.x;   // over 512*128
    int k = idx >> 7, n = idx & 127;
    float v = w1[idx];
    __nv_bfloat16 hi = __float2bfloat16(v);
    __nv_bfloat16 lo = __float2bfloat16(v - __bfloat162float(hi));
    g_w1t_hi[n * DIN + k] = hi;
    g_w1t_lo[n * DIN + k] = lo;
}

// ---------------- kernel 1: delta -> split-bf16 HMMA GEMM -> GELU ----------------
// Block: 128 pixels x 128 outputs. K=512 in 8 chunks of 64 via smem.
// 8 warps arranged 4x2; warp tile 32 rows x 64 cols.
// smem: A_hi[128][72bf16] A_lo B_hi[128][72] B_lo, pitch 144B (conflict-free ldmatrix)
#define APITCH 72               // bf16 elements per row (144 bytes)
#define SM_AHI 0
#define SM_ALO (128*144)        // 18432
#define SM_BHI (2*128*144)      // 36864
#define SM_BLO (3*128*144)      // 55296
#define ENC_SM_BYTES (4*128*144)// 73728

__global__ __launch_bounds__(256, 2) void k_enc1(const float* __restrict__ t0,
                                                 const float* __restrict__ t1,
                                                 const float* __restrict__ b1) {
    extern __shared__ char sm[];
    const uint32_t smb = smem_u32(sm);
    const int tid = threadIdx.x;
    const int wid = tid >> 5, l = tid & 31;
    const int wm = wid & 3, wn = wid >> 2;     // warp row-group (0..3), col-group (0..1)
    const int p0 = blockIdx.x * 128;

    float acc[2][8][4];
#pragma unroll
    for (int rt = 0; rt < 2; rt++)
#pragma unroll
        for (int nt = 0; nt < 8; nt++)
#pragma unroll
            for (int q = 0; q < 4; q++) acc[rt][nt][q] = 0.0f;

    // per-lane ldmatrix base offsets (within tile, bytes)
    const uint32_t a_row = (uint32_t)(wm * 32 + (l & 15));
    const uint32_t a_kof = (uint32_t)((l >> 4) * 8) * 2;
    const uint32_t b_row = (uint32_t)(wn * 64 + (l & 7));
    const uint32_t b_kof = (uint32_t)(((l >> 3) & 1) * 8) * 2;

    for (int c = 0; c < 8; c++) {
        const int kc = c * 64;
        if (c) __syncthreads();

        // stage A: delta[128 rows][64 k] -> bf16 hi/lo
#pragma unroll
        for (int it = 0; it < 8; it++) {
            int i = tid + it * 256;             // 2048 float4 groups
            int row = i >> 4, g = i & 15;       // k offset = g*4
            size_t gaddr = (size_t)(p0 + row) * DIN + kc + g * 4;
            float4 v1 = *(const float4*)(t1 + gaddr);
            float4 v0 = *(const float4*)(t0 + gaddr);
            float d0 = v1.x - v0.x, d1 = v1.y - v0.y, d2 = v1.z - v0.z, d3 = v1.w - v0.w;
            __nv_bfloat16 h0 = __float2bfloat16(d0), h1 = __float2bfloat16(d1),
                          h2 = __float2bfloat16(d2), h3 = __float2bfloat16(d3);
            __nv_bfloat16 e0 = __float2bfloat16(d0 - __bfloat162float(h0));
            __nv_bfloat16 e1 = __float2bfloat16(d1 - __bfloat162float(h1));
            __nv_bfloat16 e2 = __float2bfloat16(d2 - __bfloat162float(h2));
            __nv_bfloat16 e3 = __float2bfloat16(d3 - __bfloat162float(h3));
            uint32_t off = (uint32_t)(row * 144 + g * 8);
            *(uint2*)(sm + SM_AHI + off) = make_uint2(pk_bf16(h0, h1), pk_bf16(h2, h3));
            *(uint2*)(sm + SM_ALO + off) = make_uint2(pk_bf16(e0, e1), pk_bf16(e2, e3));
        }
        // stage B: W1^T hi/lo [128 n][64 k]
#pragma unroll
        for (int it = 0; it < 4; it++) {
            int i = tid + it * 256;             // 1024 uint4 groups
            int n = i >> 3, g = i & 7;          // k offset = g*8
            uint4 hv = *(const uint4*)(g_w1t_hi + n * DIN + kc + g * 8);
            uint4 lv = *(const uint4*)(g_w1t_lo + n * DIN + kc + g * 8);
            uint32_t off = (uint32_t)(n * 144 + g * 16);
            *(uint4*)(sm + SM_BHI + off) = hv;
            *(uint4*)(sm + SM_BLO + off) = lv;
        }
        __syncthreads();

        // compute: 4 k16 steps
#pragma unroll
        for (int ks = 0; ks < 4; ks++) {
            uint32_t ahi[2][4], alo[2][4];
#pragma unroll
            for (int rt = 0; rt < 2; rt++) {
                uint32_t aoff = (a_row + rt * 16) * 144 + ks * 32 + a_kof;
                ldsm_x4(ahi[rt], smb + SM_AHI + aoff);
                ldsm_x4(alo[rt], smb + SM_ALO + aoff);
            }
#pragma unroll
            for (int nt = 0; nt < 8; nt++) {
                uint32_t boff = (b_row + nt * 8) * 144 + ks * 32 + b_kof;
                uint32_t bhi[2], blo[2];
                ldsm_x2(bhi, smb + SM_BHI + boff);
                ldsm_x2(blo, smb + SM_BLO + boff);
#pragma unroll
                for (int rt = 0; rt < 2; rt++) {
                    mma_bf16(acc[rt][nt], ahi[rt], bhi);
                    mma_bf16(acc[rt][nt], ahi[rt], blo);
                    mma_bf16(acc[rt][nt], alo[rt], bhi);
                }
            }
        }
    }

    // epilogue: bias + exact GELU, store float2 pairs
    float2 bias[8];
#pragma unroll
    for (int nt = 0; nt < 8; nt++) {
        int cc = wn * 64 + nt * 8 + 2 * (l & 3);
        bias[nt] = make_float2(__ldg(&b1[cc]), __ldg(&b1[cc + 1]));
    }
#pragma unroll
    for (int rt = 0; rt < 2; rt++) {
        int r0 = p0 + wm * 32 + rt * 16 + (l >> 2);
#pragma unroll
        for (int nt = 0; nt < 8; nt++) {
            int cc = wn * 64 + nt * 8 + 2 * (l & 3);
            float2 o0, o1;
            o0.x = gelu_exact(acc[rt][nt][0] + bias[nt].x);
            o0.y = gelu_exact(acc[rt][nt][1] + bias[nt].y);
            o1.x = gelu_exact(acc[rt][nt][2] + bias[nt].x);
            o1.y = gelu_exact(acc[rt][nt][3] + bias[nt].y);
            *(float2*)&g_H[(size_t)r0 * H1 + cc]       = o0;
            *(float2*)&g_H[(size_t)(r0 + 8) * H1 + cc] = o1;
        }
    }
}

// ---------------- kernel 2: 7x7 block-mean pooling ----------------
__global__ __launch_bounds__(128) void k_pool() {
    int t = blockIdx.x;
    int j = threadIdx.x;
    int b = t >> 2, g = t & 3, gy = g >> 1, gx = g & 1;
    float s = 0.0f;
#pragma unroll
    for (int dy = 0; dy < 7; dy++) {
        int y = gy * 7 + dy;
#pragma unroll
        for (int dx = 0; dx < 7; dx++) {
            int x = gx * 7 + dx;
            size_t pix = (size_t)((b * HH + y) * WW + x);
            s += g_H[pix * H1 + j];
        }
    }
    g_Hbar[t * H1 + j] = s * (1.0f / 49.0f);
}

// ---------------- kernel 3: GEMM2 + VQ (8 tokens/block, 256 blocks) ----------------
#define VQ_TOKS 8
#define CBT_LD 257
#define FS_LD 65
#define SMEM_VQ_FLOATS (64*CBT_LD + VQ_TOKS*H1 + VQ_TOKS*FS_LD + KCODES + VQ_TOKS)
#define SMEM_VQ_BYTES (SMEM_VQ_FLOATS * 4)

__global__ __launch_bounds__(256) void k_vq2(const float* __restrict__ w2,
                                             const float* __restrict__ b2,
                                             const float* __restrict__ cb) {
    extern __shared__ float smv[];
    float* cbT   = smv;                        // [64][257]
    float* hbs   = cbT + 64 * CBT_LD;          // [8][128]
    float* fs    = hbs + VQ_TOKS * H1;         // [8][65]
    float* cn    = fs + VQ_TOKS * FS_LD;       // [256]
    float* fnorm = cn + KCODES;                // [8]

    const int tid = threadIdx.x;
    const int tok0 = blockIdx.x * VQ_TOKS;

    for (int li = tid; li < KCODES * EDIM; li += 256) {
        int c = li >> 6, j = li & 63;
        cbT[j * CBT_LD + c] = cb[li];
    }
    for (int li = tid; li < VQ_TOKS * H1; li += 256)
        hbs[li] = g_Hbar[tok0 * H1 + li];
    __syncthreads();

    {
        float s = 0.0f;
#pragma unroll 8
        for (int j = 0; j < EDIM; j++) {
            float v = cbT[j * CBT_LD + tid];
            s = fmaf(v, v, s);
        }
        cn[tid] = s;
    }

    // flat = Hbar @ w2 + b2
    {
        const int j = tid & 63, tg = tid >> 6;   // tg: 0..3, 2 tokens each
        float bj = b2[j];
        float acc0 = bj, acc1 = bj;
#pragma unroll 4
        for (int k = 0; k < H1; k++) {
            float wv = __ldg(&w2[k * EDIM + j]);
            acc0 = fmaf(hbs[(tg * 2 + 0) * H1 + k], wv, acc0);
            acc1 = fmaf(hbs[(tg * 2 + 1) * H1 + k], wv, acc1);
        }
        fs[(tg * 2 + 0) * FS_LD + j] = acc0;
        fs[(tg * 2 + 1) * FS_LD + j] = acc1;
    }
    __syncthreads();

    if (tid < VQ_TOKS) {
        float s = 0.0f;
#pragma unroll 8
        for (int j = 0; j < EDIM; j++) {
            float v = fs[tid * FS_LD + j];
            s = fmaf(v, v, s);
        }
        fnorm[tid] = s;
    }
    __syncthreads();

    // warp w -> token w; lane l -> codes l+32i
    const int w = tid >> 5, l = tid & 31;
    float dot[8];
#pragma unroll
    for (int i = 0; i < 8; i++) dot[i] = 0.0f;
#pragma unroll 4
    for (int j = 0; j < EDIM; j++) {
        float fj = fs[w * FS_LD + j];
#pragma unroll
        for (int i = 0; i < 8; i++)
            dot[i] = fmaf(fj, cbT[j * CBT_LD + l + 32 * i], dot[i]);
    }
    float bd = 3.4e38f; int bi = 0;
#pragma unroll
    for (int i = 0; i < 8; i++) {
        int c = l + 32 * i;
        float d = fmaf(-2.0f, dot[i], cn[c]);
        if (d < bd) { bd = d; bi = c; }
    }
    for (int off = 16; off > 0; off >>= 1) {
        float od = __shfl_down_sync(0xffffffffu, bd, off);
        int   oi = __shfl_down_sync(0xffffffffu, bi, off);
        if (od < bd || (od == bd && oi < bi)) { bd = od; bi = oi; }
    }
    if (l == 0) {
        int tok = tok0 + w;
        g_idx[tok] = bi;
        atomicAdd(&g_counts[bi], 1);
        atomicAdd(&g_loss, fnorm[w] + bd);
    }
}

// ---------------- kernel 4: perplexity + commitment + indices ----------------
__global__ __launch_bounds__(256) void k_fin(float* __restrict__ out) {
    __shared__ float r[256];
    int tid = threadIdx.x;
    float p = (float)g_counts[tid] * (1.0f / (float)NTOK);
    r[tid] = p * logf(p + 1e-10f);
    __syncthreads();
    for (int s = 128; s > 0; s >>= 1) {
        if (tid < s) r[tid] += r[tid + s];
        __syncthreads();
    }
    if (tid == 0) {
        out[OUT_PPL] = expf(-r[0]);
        out[OUT_CMT] = g_loss * (1.0f / (float)(NTOK * EDIM));
    }
    for (int i = tid; i < NTOK; i += 256) out[OUT_IDX + i] = (float)g_idx[i];
}

// ---------------- kernel 5: decoder MLP (8 tokens per block) ----------------
__global__ __launch_bounds__(256) void k_dec(const float* __restrict__ dw1,
                                             const float* __restrict__ db1,
                                             const float* __restrict__ dw2,
                                             const float* __restrict__ db2,
                                             const float* __restrict__ cb) {
    __shared__ float q[8][EDIM];
    __shared__ float hd[8][H1];
    int tid = threadIdx.x;
    int tb = blockIdx.x * 8;

    for (int li = tid; li < 8 * EDIM; li += 256) {
        int tt = li >> 6, j = li & 63;
        q[tt][j] = cb[g_idx[tb + tt] * EDIM + j];
    }
    __syncthreads();
#pragma unroll
    for (int i = 0; i < 4; i++) {
        int li = tid + i * 256;
        int tt = li >> 7, j = li & 127;
        float s = db1[j];
#pragma unroll 8
        for (int k = 0; k < EDIM; k++) s = fmaf(q[tt][k], dw1[k * H1 + j], s);
        hd[tt][j] = gelu_exact(s);
    }
    __syncthreads();

    float a0[8], a1[8];
#pragma unroll
    for (int tt = 0; tt < 8; tt++) { a0[tt] = 0.0f; a1[tt] = 0.0f; }
#pragma unroll 4
    for (int k = 0; k < H1; k++) {
        float w0 = dw2[k * DIN + tid];
        float w1v = dw2[k * DIN + 256 + tid];
#pragma unroll
        for (int tt = 0; tt < 8; tt++) {
            float h = hd[tt][k];
            a0[tt] = fmaf(h, w0, a0[tt]);
            a1[tt] = fmaf(h, w1v, a1[tt]);
        }
    }
    float bb0 = db2[tid], bb1 = db2[tid + 256];
#pragma unroll
    for (int tt = 0; tt < 8; tt++) {
        g_S[(size_t)(tb + tt) * DIN + tid]       = a0[tt] + bb0;
        g_S[(size_t)(tb + tt) * DIN + 256 + tid] = a1[tt] + bb1;
    }
}

// ---------------- kernel 6: 2x2 -> 14x14 bilinear ----------------
__global__ __launch_bounds__(256) void k_up(float* __restrict__ out) {
    __shared__ float Arow[DIN], Brow[DIN];
    int b = blockIdx.x, y = blockIdx.y;
    int tid = threadIdx.x;

    float sy = (y + 0.5f) * (1.0f / 7.0f) - 0.5f;
    int iy0 = (int)floorf(sy);
    float fy = sy - (float)iy0;
    int y0 = min(max(iy0, 0), 1);
    int y1 = min(max(iy0 + 1, 0), 1);

    const float* S0a = &g_S[(size_t)(b * 4 + y0 * 2 + 0) * DIN];
    const float* S1a = &g_S[(size_t)(b * 4 + y1 * 2 + 0) * DIN];
    const float* S0b = &g_S[(size_t)(b * 4 + y0 * 2 + 1) * DIN];
    const float* S1b = &g_S[(size_t)(b * 4 + y1 * 2 + 1) * DIN];
    float wy0 = 1.0f - fy;
    for (int c = tid; c < DIN; c += 256) {
        Arow[c] = wy0 * S0a[c] + fy * S1a[c];
        Brow[c] = wy0 * S0b[c] + fy * S1b[c];
    }
    __syncthreads();

#pragma unroll
    for (int x = 0; x < 14; x++) {
        float sx = (x + 0.5f) * (1.0f / 7.0f) - 0.5f;
        int ix0 = (int)floorf(sx);
        float fx = sx - (float)ix0;
        int x0 = min(max(ix0, 0), 1);
        int x1 = min(max(ix0 + 1, 0), 1);
        float wx0 = 1.0f - fx;
        float* o = out + ((size_t)((b * HH + y) * WW + x)) * DIN;
        for (int c = tid; c < DIN; c += 256) {
            float v0 = x0 ? Brow[c] : Arow[c];
            float v1 = x1 ? Brow[c] : Arow[c];
            o[c] = wx0 * v0 + fx * v1;
        }
    }
}

// ---------------- launch ----------------
extern "C" void kernel_launch(void* const* d_in, const int* in_sizes, int n_in,
                              void* d_out, int out_size) {
    const float* t0  = (const float*)d_in[0];
    const float* t1  = (const float*)d_in[1];
    const float* ew1 = (const float*)d_in[2];
    const float* eb1 = (const float*)d_in[3];
    const float* ew2 = (const float*)d_in[4];
    const float* eb2 = (const float*)d_in[5];
    const float* dw1 = (const float*)d_in[6];
    const float* db1 = (const float*)d_in[7];
    const float* dw2 = (const float*)d_in[8];
    const float* db2 = (const float*)d_in[9];
    const float* cb  = (const float*)d_in[10];
    float* out = (float*)d_out;

    cudaFuncSetAttribute(k_enc1, cudaFuncAttributeMaxDynamicSharedMemorySize, ENC_SM_BYTES);
    cudaFuncSetAttribute(k_vq2, cudaFuncAttributeMaxDynamicSharedMemorySize, SMEM_VQ_BYTES);

    k_init<<<1, 256>>>();
    k_prep<<<DIN * H1 / 256, 256>>>(ew1);
    k_enc1<<<NPIX / 128, 256, ENC_SM_BYTES>>>(t0, t1, eb1);
    k_pool<<<NTOK, 128>>>();
    k_vq2<<<NTOK / VQ_TOKS, 256, SMEM_VQ_BYTES>>>(ew2, eb2, cb);
    k_fin<<<1, 256>>>(out);
    k_dec<<<NTOK / 8, 256>>>(dw1, db1, dw2, db2, cb);
    k_up<<<dim3(BATCH, HH), 256>>>(out);
}

// round 9
// speedup vs baseline: 2.1326x; 1.0464x over previous
#include <cuda_runtime.h>
#include <cuda_bf16.h>
#include <math.h>
#include <stdint.h>

// ---------------- problem constants ----------------
#define BATCH 512
#define HH 14
#define WW 14
#define DIN 512
#define EDIM 64
#define KCODES 256
#define NPIX (BATCH*HH*WW)          // 100352
#define NTOK (BATCH*4)              // 2048
#define H1 128                      // 2*EDIM

#define OUT_PPL ((size_t)NPIX*DIN)
#define OUT_CMT (OUT_PPL+1)
#define OUT_IDX (OUT_PPL+2)

// ---------------- scratch (static device memory; no allocations) ----------------
__device__ float g_H[(size_t)NPIX*H1];      // gelu(delta@W1+b1)
__device__ float g_Hbar[NTOK*H1];
__device__ float g_S[NTOK*DIN];
__device__ int   g_idx[NTOK];
__device__ int   g_counts[KCODES];
__device__ float g_loss;
// W1^T split into bf16 hi/lo: [n=128][k=512]
__device__ __nv_bfloat16 g_w1t_hi[H1*DIN];
__device__ __nv_bfloat16 g_w1t_lo[H1*DIN];

__device__ __forceinline__ float gelu_exact(float x) {
    return 0.5f * x * (1.0f + erff(x * 0.70710678118654752440f));
}

__device__ __forceinline__ uint32_t smem_u32(const void* p) {
    uint32_t a;
    asm("{ .reg .u64 t; cvta.to.shared.u64 t, %1; cvt.u32.u64 %0, t; }" : "=r"(a) : "l"(p));
    return a;
}

// baseline-PTX tensor ops (valid on plain sm_103 — no 'a' features)
__device__ __forceinline__ void ldsm_x4(uint32_t* r, uint32_t addr) {
    asm volatile("ldmatrix.sync.aligned.m8n8.x4.shared.b16 {%0,%1,%2,%3}, [%4];"
                 : "=r"(r[0]), "=r"(r[1]), "=r"(r[2]), "=r"(r[3]) : "r"(addr));
}
__device__ __forceinline__ void mma_bf16(float* d, const uint32_t* a, const uint32_t* b) {
    asm volatile("mma.sync.aligned.m16n8k16.row.col.f32.bf16.bf16.f32 "
                 "{%0,%1,%2,%3}, {%4,%5,%6,%7}, {%8,%9}, {%0,%1,%2,%3};"
                 : "+f"(d[0]), "+f"(d[1]), "+f"(d[2]), "+f"(d[3])
                 : "r"(a[0]), "r"(a[1]), "r"(a[2]), "r"(a[3]), "r"(b[0]), "r"(b[1]));
}
__device__ __forceinline__ uint32_t pk_bf16(__nv_bfloat16 a, __nv_bfloat16 b) {
    return (uint32_t)__bfloat16_as_ushort(a) | ((uint32_t)__bfloat16_as_ushort(b) << 16);
}
__device__ __forceinline__ void cp_async16(uint32_t dst, const void* src) {
    asm volatile("cp.async.ca.shared.global [%0], [%1], 16;" :: "r"(dst), "l"(src) : "memory");
}
#define CP_COMMIT()  asm volatile("cp.async.commit_group;" ::: "memory")
#define CP_WAIT0()   asm volatile("cp.async.wait_group 0;" ::: "memory")

// ---------------- kernel 0: zero accumulators ----------------
__global__ void k_init() {
    int t = threadIdx.x;
    if (t < KCODES) g_counts[t] = 0;
    if (t == 0) g_loss = 0.0f;
}

// ---------------- kernel 0b: pre-split W1^T into bf16 hi/lo ----------------
__global__ __launch_bounds__(256) void k_prep(const float* __restrict__ w1) {
    int idx = blockIdx.x * 256 + threadIdx.x;   // over 512*128
    int k = idx >> 7, n = idx & 127;
    float v = w1[idx];
    __nv_bfloat16 hi = __float2bfloat16(v);
    __nv_bfloat16 lo = __float2bfloat16(v - __bfloat162float(hi));
    g_w1t_hi[n * DIN + k] = hi;
    g_w1t_lo[n * DIN + k] = lo;
}

// ---------------- kernel 1: delta -> split-bf16 HMMA GEMM -> GELU ----------------
// Block: 128 pixels x 128 outputs. K=512 in 8 chunks of 64 via smem.
// 8 warps arranged 4x2; warp tile 32 rows x 64 cols.
// smem: A_hi[128][144B] A_lo B_hi B_lo; pitch 144B (conflict-free ldmatrix)
#define SM_AHI 0
#define SM_ALO (128*144)        // 18432
#define SM_BHI (2*128*144)      // 36864
#define SM_BLO (3*128*144)      // 55296
#define ENC_SM_BYTES (4*128*144)// 73728

__global__ __launch_bounds__(256, 2) void k_enc1(const float* __restrict__ t0,
                                                 const float* __restrict__ t1,
                                                 const float* __restrict__ b1) {
    extern __shared__ char sm[];
    const uint32_t smb = smem_u32(sm);
    const int tid = threadIdx.x;
    const int wid = tid >> 5, l = tid & 31;
    const int wm = wid & 3, wn = wid >> 2;     // warp row-group (0..3), col-group (0..1)
    const int p0 = blockIdx.x * 128;

    float acc[2][8][4];
#pragma unroll
    for (int rt = 0; rt < 2; rt++)
#pragma unroll
        for (int nt = 0; nt < 8; nt++)
#pragma unroll
            for (int q = 0; q < 4; q++) acc[rt][nt][q] = 0.0f;

    // per-lane ldmatrix base offsets
    const uint32_t a_row = (uint32_t)(wm * 32 + (l & 15));
    const uint32_t a_kof = (uint32_t)((l >> 4) * 8) * 2;
    // x4 B: matrices [nt_even,k0][nt_even,k1][nt_odd,k0][nt_odd,k1]
    const uint32_t b_row4 = (uint32_t)(wn * 64 + ((l >> 4) << 3) + (l & 7));
    const uint32_t b_k4   = (uint32_t)(((l >> 3) & 1) * 16);

    // per-thread staging indices (constant across chunks)
    const int b_n = (tid >> 3);            // only valid for first 128*... see loop
    (void)b_n;

    for (int c = 0; c < 8; c++) {
        const int kc = c * 64;
        if (c) __syncthreads();

        // stage B via cp.async: 1024 16B lines per tensor, 4 per thread each
#pragma unroll
        for (int it = 0; it < 4; it++) {
            int i = tid + it * 256;             // 1024 lines
            int n = i >> 3, g = i & 7;          // k offset = g*8 elements
            uint32_t off = (uint32_t)(n * 144 + g * 16);
            cp_async16(smb + SM_BHI + off, g_w1t_hi + n * DIN + kc + g * 8);
            cp_async16(smb + SM_BLO + off, g_w1t_lo + n * DIN + kc + g * 8);
        }
        CP_COMMIT();

        // stage A: delta[128 rows][64 k] -> bf16 hi/lo (LDGs hoisted in pairs)
#pragma unroll
        for (int half = 0; half < 4; half++) {
            float4 v1[2], v0[2];
            int rows[2], gs[2];
#pragma unroll
            for (int u = 0; u < 2; u++) {
                int i = tid + (half * 2 + u) * 256;     // 2048 float4 groups
                rows[u] = i >> 4; gs[u] = i & 15;       // k offset = g*4
                size_t gaddr = (size_t)(p0 + rows[u]) * DIN + kc + gs[u] * 4;
                v1[u] = *(const float4*)(t1 + gaddr);
                v0[u] = *(const float4*)(t0 + gaddr);
            }
#pragma unroll
            for (int u = 0; u < 2; u++) {
                float d0 = v1[u].x - v0[u].x, d1 = v1[u].y - v0[u].y,
                      d2 = v1[u].z - v0[u].z, d3 = v1[u].w - v0[u].w;
                __nv_bfloat16 h0 = __float2bfloat16(d0), h1 = __float2bfloat16(d1),
                              h2 = __float2bfloat16(d2), h3 = __float2bfloat16(d3);
                __nv_bfloat16 e0 = __float2bfloat16(d0 - __bfloat162float(h0));
                __nv_bfloat16 e1 = __float2bfloat16(d1 - __bfloat162float(h1));
                __nv_bfloat16 e2 = __float2bfloat16(d2 - __bfloat162float(h2));
                __nv_bfloat16 e3 = __float2bfloat16(d3 - __bfloat162float(h3));
                uint32_t off = (uint32_t)(rows[u] * 144 + gs[u] * 8);
                *(uint2*)(sm + SM_AHI + off) = make_uint2(pk_bf16(h0, h1), pk_bf16(h2, h3));
                *(uint2*)(sm + SM_ALO + off) = make_uint2(pk_bf16(e0, e1), pk_bf16(e2, e3));
            }
        }
        CP_WAIT0();
        __syncthreads();

        // compute: 4 k16 steps
#pragma unroll
        for (int ks = 0; ks < 4; ks++) {
            uint32_t ahi[2][4], alo[2][4];
#pragma unroll
            for (int rt = 0; rt < 2; rt++) {
                uint32_t aoff = (a_row + rt * 16) * 144 + ks * 32 + a_kof;
                ldsm_x4(ahi[rt], smb + SM_AHI + aoff);
                ldsm_x4(alo[rt], smb + SM_ALO + aoff);
            }
#pragma unroll
            for (int ntp = 0; ntp < 4; ntp++) {
                uint32_t boff = (b_row4 + ntp * 16) * 144 + ks * 32 + b_k4;
                uint32_t bhi[4], blo[4];
                ldsm_x4(bhi, smb + SM_BHI + boff);
                ldsm_x4(blo, smb + SM_BLO + boff);
#pragma unroll
                for (int h = 0; h < 2; h++) {           // even/odd nt of the pair
                    int nt = ntp * 2 + h;
#pragma unroll
                    for (int rt = 0; rt < 2; rt++) {
                        mma_bf16(acc[rt][nt], ahi[rt], bhi + 2 * h);
                        mma_bf16(acc[rt][nt], ahi[rt], blo + 2 * h);
                        mma_bf16(acc[rt][nt], alo[rt], bhi + 2 * h);
                    }
                }
            }
        }
    }

    // epilogue: bias + exact GELU, store float2 pairs
    float2 bias[8];
#pragma unroll
    for (int nt = 0; nt < 8; nt++) {
        int cc = wn * 64 + nt * 8 + 2 * (l & 3);
        bias[nt] = make_float2(__ldg(&b1[cc]), __ldg(&b1[cc + 1]));
    }
#pragma unroll
    for (int rt = 0; rt < 2; rt++) {
        int r0 = p0 + wm * 32 + rt * 16 + (l >> 2);
#pragma unroll
        for (int nt = 0; nt < 8; nt++) {
            int cc = wn * 64 + nt * 8 + 2 * (l & 3);
            float2 o0, o1;
            o0.x = gelu_exact(acc[rt][nt][0] + bias[nt].x);
            o0.y = gelu_exact(acc[rt][nt][1] + bias[nt].y);
            o1.x = gelu_exact(acc[rt][nt][2] + bias[nt].x);
            o1.y = gelu_exact(acc[rt][nt][3] + bias[nt].y);
            *(float2*)&g_H[(size_t)r0 * H1 + cc]       = o0;
            *(float2*)&g_H[(size_t)(r0 + 8) * H1 + cc] = o1;
        }
    }
}

// ---------------- kernel 2: 7x7 block-mean pooling ----------------
__global__ __launch_bounds__(128) void k_pool() {
    int t = blockIdx.x;
    int j = threadIdx.x;
    int b = t >> 2, g = t & 3, gy = g >> 1, gx = g & 1;
    float s = 0.0f;
#pragma unroll
    for (int dy = 0; dy < 7; dy++) {
        int y = gy * 7 + dy;
#pragma unroll
        for (int dx = 0; dx < 7; dx++) {
            int x = gx * 7 + dx;
            size_t pix = (size_t)((b * HH + y) * WW + x);
            s += g_H[pix * H1 + j];
        }
    }
    g_Hbar[t * H1 + j] = s * (1.0f / 49.0f);
}

// ---------------- kernel 3: GEMM2 + VQ (8 tokens/block, 256 blocks) ----------------
#define VQ_TOKS 8
#define CBT_LD 257
#define FS_LD 65
#define SMEM_VQ_FLOATS (64*CBT_LD + VQ_TOKS*H1 + VQ_TOKS*FS_LD + KCODES + VQ_TOKS)
#define SMEM_VQ_BYTES (SMEM_VQ_FLOATS * 4)

__global__ __launch_bounds__(256) void k_vq2(const float* __restrict__ w2,
                                             const float* __restrict__ b2,
                                             const float* __restrict__ cb) {
    extern __shared__ float smv[];
    float* cbT   = smv;                        // [64][257]
    float* hbs   = cbT + 64 * CBT_LD;          // [8][128]
    float* fs    = hbs + VQ_TOKS * H1;         // [8][65]
    float* cn    = fs + VQ_TOKS * FS_LD;       // [256]
    float* fnorm = cn + KCODES;                // [8]

    const int tid = threadIdx.x;
    const int tok0 = blockIdx.x * VQ_TOKS;

    for (int li = tid; li < KCODES * EDIM; li += 256) {
        int c = li >> 6, j = li & 63;
        cbT[j * CBT_LD + c] = cb[li];
    }
    for (int li = tid; li < VQ_TOKS * H1; li += 256)
        hbs[li] = g_Hbar[tok0 * H1 + li];
    __syncthreads();

    {
        float s = 0.0f;
#pragma unroll 8
        for (int j = 0; j < EDIM; j++) {
            float v = cbT[j * CBT_LD + tid];
            s = fmaf(v, v, s);
        }
        cn[tid] = s;
    }

    // flat = Hbar @ w2 + b2
    {
        const int j = tid & 63, tg = tid >> 6;   // tg: 0..3, 2 tokens each
        float bj = b2[j];
        float acc0 = bj, acc1 = bj;
#pragma unroll 4
        for (int k = 0; k < H1; k++) {
            float wv = __ldg(&w2[k * EDIM + j]);
            acc0 = fmaf(hbs[(tg * 2 + 0) * H1 + k], wv, acc0);
            acc1 = fmaf(hbs[(tg * 2 + 1) * H1 + k], wv, acc1);
        }
        fs[(tg * 2 + 0) * FS_LD + j] = acc0;
        fs[(tg * 2 + 1) * FS_LD + j] = acc1;
    }
    __syncthreads();

    if (tid < VQ_TOKS) {
        float s = 0.0f;
#pragma unroll 8
        for (int j = 0; j < EDIM; j++) {
            float v = fs[tid * FS_LD + j];
            s = fmaf(v, v, s);
        }
        fnorm[tid] = s;
    }
    __syncthreads();

    // warp w -> token w; lane l -> codes l+32i
    const int w = tid >> 5, l = tid & 31;
    float dot[8];
#pragma unroll
    for (int i = 0; i < 8; i++) dot[i] = 0.0f;
#pragma unroll 4
    for (int j = 0; j < EDIM; j++) {
        float fj = fs[w * FS_LD + j];
#pragma unroll
        for (int i = 0; i < 8; i++)
            dot[i] = fmaf(fj, cbT[j * CBT_LD + l + 32 * i], dot[i]);
    }
    float bd = 3.4e38f; int bi = 0;
#pragma unroll
    for (int i = 0; i < 8; i++) {
        int c = l + 32 * i;
        float d = fmaf(-2.0f, dot[i], cn[c]);
        if (d < bd) { bd = d; bi = c; }
    }
    for (int off = 16; off > 0; off >>= 1) {
        float od = __shfl_down_sync(0xffffffffu, bd, off);
        int   oi = __shfl_down_sync(0xffffffffu, bi, off);
        if (od < bd || (od == bd && oi < bi)) { bd = od; bi = oi; }
    }
    if (l == 0) {
        int tok = tok0 + w;
        g_idx[tok] = bi;
        atomicAdd(&g_counts[bi], 1);
        atomicAdd(&g_loss, fnorm[w] + bd);
    }
}

// ---------------- kernel 4: perplexity + commitment + indices ----------------
__global__ __launch_bounds__(256) void k_fin(float* __restrict__ out) {
    __shared__ float r[256];
    int tid = threadIdx.x;
    float p = (float)g_counts[tid] * (1.0f / (float)NTOK);
    r[tid] = p * logf(p + 1e-10f);
    __syncthreads();
    for (int s = 128; s > 0; s >>= 1) {
        if (tid < s) r[tid] += r[tid + s];
        __syncthreads();
    }
    if (tid == 0) {
        out[OUT_PPL] = expf(-r[0]);
        out[OUT_CMT] = g_loss * (1.0f / (float)(NTOK * EDIM));
    }
    for (int i = tid; i < NTOK; i += 256) out[OUT_IDX + i] = (float)g_idx[i];
}

// ---------------- kernel 5: decoder MLP (8 tokens per block) ----------------
__global__ __launch_bounds__(256) void k_dec(const float* __restrict__ dw1,
                                             const float* __restrict__ db1,
                                             const float* __restrict__ dw2,
                                             const float* __restrict__ db2,
                                             const float* __restrict__ cb) {
    __shared__ float q[8][EDIM];
    __shared__ float hd[8][H1];
    int tid = threadIdx.x;
    int tb = blockIdx.x * 8;

    for (int li = tid; li < 8 * EDIM; li += 256) {
        int tt = li >> 6, j = li & 63;
        q[tt][j] = cb[g_idx[tb + tt] * EDIM + j];
    }
    __syncthreads();
#pragma unroll
    for (int i = 0; i < 4; i++) {
        int li = tid + i * 256;
        int tt = li >> 7, j = li & 127;
        float s = db1[j];
#pragma unroll 8
        for (int k = 0; k < EDIM; k++) s = fmaf(q[tt][k], dw1[k * H1 + j], s);
        hd[tt][j] = gelu_exact(s);
    }
    __syncthreads();

    float a0[8], a1[8];
#pragma unroll
    for (int tt = 0; tt < 8; tt++) { a0[tt] = 0.0f; a1[tt] = 0.0f; }
#pragma unroll 4
    for (int k = 0; k < H1; k++) {
        float w0 = dw2[k * DIN + tid];
        float w1v = dw2[k * DIN + 256 + tid];
#pragma unroll
        for (int tt = 0; tt < 8; tt++) {
            float h = hd[tt][k];
            a0[tt] = fmaf(h, w0, a0[tt]);
            a1[tt] = fmaf(h, w1v, a1[tt]);
        }
    }
    float bb0 = db2[tid], bb1 = db2[tid + 256];
#pragma unroll
    for (int tt = 0; tt < 8; tt++) {
        g_S[(size_t)(tb + tt) * DIN + tid]       = a0[tt] + bb0;
        g_S[(size_t)(tb + tt) * DIN + 256 + tid] = a1[tt] + bb1;
    }
}

// ---------------- kernel 6: 2x2 -> 14x14 bilinear ----------------
__global__ __launch_bounds__(256) void k_up(float* __restrict__ out) {
    __shared__ float Arow[DIN], Brow[DIN];
    int b = blockIdx.x, y = blockIdx.y;
    int tid = threadIdx.x;

    float sy = (y + 0.5f) * (1.0f / 7.0f) - 0.5f;
    int iy0 = (int)floorf(sy);
    float fy = sy - (float)iy0;
    int y0 = min(max(iy0, 0), 1);
    int y1 = min(max(iy0 + 1, 0), 1);

    const float* S0a = &g_S[(size_t)(b * 4 + y0 * 2 + 0) * DIN];
    const float* S1a = &g_S[(size_t)(b * 4 + y1 * 2 + 0) * DIN];
    const float* S0b = &g_S[(size_t)(b * 4 + y0 * 2 + 1) * DIN];
    const float* S1b = &g_S[(size_t)(b * 4 + y1 * 2 + 1) * DIN];
    float wy0 = 1.0f - fy;
    for (int c = tid; c < DIN; c += 256) {
        Arow[c] = wy0 * S0a[c] + fy * S1a[c];
        Brow[c] = wy0 * S0b[c] + fy * S1b[c];
    }
    __syncthreads();

#pragma unroll
    for (int x = 0; x < 14; x++) {
        float sx = (x + 0.5f) * (1.0f / 7.0f) - 0.5f;
        int ix0 = (int)floorf(sx);
        float fx = sx - (float)ix0;
        int x0 = min(max(ix0, 0), 1);
        int x1 = min(max(ix0 + 1, 0), 1);
        float wx0 = 1.0f - fx;
        float* o = out + ((size_t)((b * HH + y) * WW + x)) * DIN;
        for (int c = tid; c < DIN; c += 256) {
            float v0 = x0 ? Brow[c] : Arow[c];
            float v1 = x1 ? Brow[c] : Arow[c];
            o[c] = wx0 * v0 + fx * v1;
        }
    }
}

// ---------------- launch ----------------
extern "C" void kernel_launch(void* const* d_in, const int* in_sizes, int n_in,
                              void* d_out, int out_size) {
    const float* t0  = (const float*)d_in[0];
    const float* t1  = (const float*)d_in[1];
    const float* ew1 = (const float*)d_in[2];
    const float* eb1 = (const float*)d_in[3];
    const float* ew2 = (const float*)d_in[4];
    const float* eb2 = (const float*)d_in[5];
    const float* dw1 = (const float*)d_in[6];
    const float* db1 = (const float*)d_in[7];
    const float* dw2 = (const float*)d_in[8];
    const float* db2 = (const float*)d_in[9];
    const float* cb  = (const float*)d_in[10];
    float* out = (float*)d_out;

    cudaFuncSetAttribute(k_enc1, cudaFuncAttributeMaxDynamicSharedMemorySize, ENC_SM_BYTES);
    cudaFuncSetAttribute(k_vq2, cudaFuncAttributeMaxDynamicSharedMemorySize, SMEM_VQ_BYTES);

    k_init<<<1, 256>>>();
    k_prep<<<DIN * H1 / 256, 256>>>(ew1);
    k_enc1<<<NPIX / 128, 256, ENC_SM_BYTES>>>(t0, t1, eb1);
    k_pool<<<NTOK, 128>>>();
    k_vq2<<<NTOK / VQ_TOKS, 256, SMEM_VQ_BYTES>>>(ew2, eb2, cb);
    k_fin<<<1, 256>>>(out);
    k_dec<<<NTOK / 8, 256>>>(dw1, db1, dw2, db2, cb);
    k_up<<<dim3(BATCH, HH), 256>>>(out);
}